// round 17
// baseline (speedup 1.0000x reference)
#include <cuda_runtime.h>
#include <cuda_bf16.h>
#include <cstdint>
#include <cstddef>

// Pairwise Euclidean distance, B=8192, K=256, D=3072, fp32.
// out[b,k] = sqrt(max(||x||^2 + ||c||^2 - 2 x.c, eps))
// R17 = R8 main kernel VERBATIM (best measured: 61.8us main) + fast
// warp-per-row prepass (4.5us -> ~1.2us). No other changes.

#define BB 8192
#define KK 256
#define DD 3072
#define BM 128
#define BN 128
#define BK 32
#define NT (DD / BK)            // 96 k-tiles
#define NTG (NT / 2)            // 48 tiles per group
#define NTHREADS 512
#define EPS_F 1e-12f

#define ROW_B 80                // 32 bf16 + pad: ldmatrix conflict-free
#define TILE_B (128 * ROW_B)    // 10240
#define STAGE_B (2 * TILE_B)    // 20480 (A then B)
#define NSTAGE 8                // global ring; 4 per parity group
#define OFF_XSQ  (NSTAGE * STAGE_B)          // 163840
#define OFF_CSQ  (OFF_XSQ + 512)
#define SMEM_BYTES (OFF_CSQ + 512)           // 164864
#define STASH_STRIDE 132

__device__ __nv_bfloat16 g_cb[KK * DD];   // centers bf16
__device__ float g_csq[KK];               // ||c||^2

static __device__ __forceinline__ uint32_t s2u(const void* p) {
    uint32_t a;
    asm("{.reg .u64 t; cvta.to.shared.u64 t, %1; cvt.u32.u64 %0, t;}"
        : "=r"(a) : "l"(p));
    return a;
}

#define LDSM_X4(r0, r1, r2, r3, a)                                            \
    asm volatile("ldmatrix.sync.aligned.m8n8.x4.shared.b16 {%0,%1,%2,%3}, [%4];" \
                 : "=r"(r0), "=r"(r1), "=r"(r2), "=r"(r3) : "r"(a))

#define GBAR(id)                                                              \
    asm volatile("bar.sync %0, 256;" :: "r"(id) : "memory")

// ---------------- prepass: warp-per-row, high-MLP (fast) ----------------
// 32 blocks x 256 threads: warp w of block b handles row b*8+w.
// Each lane: 24 float4 (MLP=24 -> latency fully overlapped).
__global__ void __launch_bounds__(256, 8)
prep_c_fast(const float* __restrict__ C)
{
    const int wid  = threadIdx.x >> 5;
    const int lane = threadIdx.x & 31;
    const int row  = blockIdx.x * 8 + wid;           // 0..255
    const float4* src = reinterpret_cast<const float4*>(C + (size_t)row * DD);
    uint2* dst = reinterpret_cast<uint2*>(g_cb + (size_t)row * DD);
    float s = 0.f;
    #pragma unroll
    for (int j = 0; j < 24; j++) {                   // 768 float4 per row
        const int q = lane + j * 32;
        float4 v = src[q];
        s += v.x * v.x + v.y * v.y + v.z * v.z + v.w * v.w;
        __nv_bfloat162 p0 = __float22bfloat162_rn(make_float2(v.x, v.y));
        __nv_bfloat162 p1 = __float22bfloat162_rn(make_float2(v.z, v.w));
        uint2 u;
        u.x = *reinterpret_cast<uint32_t*>(&p0);
        u.y = *reinterpret_cast<uint32_t*>(&p1);
        dst[q] = u;
    }
    #pragma unroll
    for (int o = 16; o > 0; o >>= 1)
        s += __shfl_xor_sync(0xFFFFFFFFu, s, o);
    if (lane == 0) g_csq[row] = s;
}

// ---------------- main GEMM (R8 verbatim) ----------------
__global__ void __launch_bounds__(NTHREADS, 1)
rbf_dual_kernel(const float* __restrict__ X, float* __restrict__ out)
{
    extern __shared__ __align__(16) char smem[];
    const uint32_t sb = s2u(smem);
    const int tid  = threadIdx.x;
    const int wid  = tid >> 5;
    const int lane = tid & 31;
    const int bm = blockIdx.y;
    const int bn = blockIdx.x;

    const int g   = wid >> 3;          // k-parity group 0/1
    const int gt  = tid & 255;         // thread id within group
    const int bar = g + 1;             // named barrier id

    float* xsq_s = (float*)(smem + OFF_XSQ);
    float* csq_s = (float*)(smem + OFF_CSQ);
    if (tid < 128) {
        xsq_s[tid] = 0.f;
        csq_s[tid] = g_csq[bn * BN + tid];
    }
    __syncthreads();

    // group stage base: tile i (group-local, global kt=2i+g) -> stage g + 2*(i&3)
    const uint32_t sbg = sb + (uint32_t)g * STAGE_B;

    // ---- A producer (per group): 4 chunks/thread/tile ----
    const int ar = gt >> 3;            // base row 0..31 (rows ar+32j)
    const int c4 = gt & 7;
    const float* gA = X + (size_t)(bm * BM) * DD;
    float4 ra[4];
    float xs[4] = {0.f, 0.f, 0.f, 0.f};

    auto ldgA = [&](int i) {           // tile i -> kt = 2i+g
        const int kt = 2 * i + g;
        #pragma unroll
        for (int j = 0; j < 4; j++)
            ra[j] = *reinterpret_cast<const float4*>(
                gA + (size_t)(ar + 32 * j) * DD + kt * BK + c4 * 4);
    };
    auto stsA = [&](int i) {
        const uint32_t base = sbg + (uint32_t)(i & 3) * (2 * STAGE_B);
        #pragma unroll
        for (int j = 0; j < 4; j++) {
            float4 v = ra[j];
            xs[j] += v.x * v.x + v.y * v.y + v.z * v.z + v.w * v.w;
            __nv_bfloat162 q0 = __float22bfloat162_rn(make_float2(v.x, v.y));
            __nv_bfloat162 q1 = __float22bfloat162_rn(make_float2(v.z, v.w));
            asm volatile("st.shared.v2.b32 [%0], {%1,%2};"
                         :: "r"(base + (uint32_t)(ar + 32 * j) * ROW_B
                               + (uint32_t)c4 * 8),
                            "r"(*reinterpret_cast<uint32_t*>(&q0)),
                            "r"(*reinterpret_cast<uint32_t*>(&q1)) : "memory");
        }
    };

    // ---- B producer (per group): cp.async, 2 chunks/thread/tile ----
    const int br = gt >> 2;            // rows br, br+64
    const int bc = gt & 3;             // 16B chunk in 64B row
    const __nv_bfloat16* gB = g_cb + (size_t)(bn * BN) * DD;
    auto cpB = [&](int i) {
        const int kt = 2 * i + g;
        const uint32_t base = sbg + (uint32_t)(i & 3) * (2 * STAGE_B) + TILE_B;
        #pragma unroll
        for (int h = 0; h < 2; h++) {
            const int row = br + 64 * h;
            const uint32_t dst = base + (uint32_t)row * ROW_B + (uint32_t)bc * 16;
            asm volatile("cp.async.cg.shared.global [%0], [%1], 16;"
                         :: "r"(dst),
                            "l"(gB + (size_t)row * DD + kt * BK + bc * 8) : "memory");
        }
        asm volatile("cp.async.commit_group;" ::: "memory");
    };

    // ---- compute mapping: per group 4(M)x2(N) warps, warp tile 32x64 ----
    const int w8 = wid & 7;
    const int wm = w8 & 3;
    const int wn = w8 >> 2;
    const int fr = lane >> 2;
    const int fc = (lane & 3) * 2;
    const int lg = lane >> 3;
    const int ri = lane & 7;
    const uint32_t lm_off = (uint32_t)(((lg & 1) * 8 + ri) * ROW_B + (lg >> 1) * 16);

    float acc[2][8][4];
    #pragma unroll
    for (int i = 0; i < 2; i++)
        #pragma unroll
        for (int j = 0; j < 8; j++)
            #pragma unroll
            for (int q = 0; q < 4; q++) acc[i][j][q] = 0.f;

    // ---- prologue (group-local) ----
    ldgA(0);
    cpB(0);
    stsA(0);
    ldgA(1);
    cpB(1);
    asm volatile("cp.async.wait_group 1;" ::: "memory");
    GBAR(bar);

    // ---- mainloop: 48 group-local tiles ----
    #pragma unroll 1
    for (int i = 0; i < NTG; i++) {
        const uint32_t st = sbg + (uint32_t)(i & 3) * (2 * STAGE_B);
        const uint32_t stA = st + (uint32_t)(wm * 32 * ROW_B) + lm_off;
        const uint32_t stB = st + (uint32_t)TILE_B + (uint32_t)(wn * 64 * ROW_B) + lm_off;

        #pragma unroll
        for (int ks = 0; ks < 2; ks++) {
            const uint32_t kof = (uint32_t)ks * 32;
            uint32_t a[2][4], b[4][4];
            LDSM_X4(a[0][0], a[0][1], a[0][2], a[0][3], stA + kof);
            LDSM_X4(a[1][0], a[1][1], a[1][2], a[1][3], stA + kof + 16 * ROW_B);
            LDSM_X4(b[0][0], b[0][1], b[0][2], b[0][3], stB + kof);
            LDSM_X4(b[1][0], b[1][1], b[1][2], b[1][3], stB + kof + 16 * ROW_B);
            LDSM_X4(b[2][0], b[2][1], b[2][2], b[2][3], stB + kof + 32 * ROW_B);
            LDSM_X4(b[3][0], b[3][1], b[3][2], b[3][3], stB + kof + 48 * ROW_B);
            #pragma unroll
            for (int im = 0; im < 2; im++)
                #pragma unroll
                for (int j = 0; j < 8; j++) {
                    const int jb = j >> 1, pp = j & 1;
                    asm volatile(
                        "mma.sync.aligned.m16n8k16.row.col.f32.bf16.bf16.f32 "
                        "{%0,%1,%2,%3}, {%4,%5,%6,%7}, {%8,%9}, {%0,%1,%2,%3};\n"
                        : "+f"(acc[im][j][0]), "+f"(acc[im][j][1]),
                          "+f"(acc[im][j][2]), "+f"(acc[im][j][3])
                        : "r"(a[im][0]), "r"(a[im][1]), "r"(a[im][2]), "r"(a[im][3]),
                          "r"(b[jb][pp]), "r"(b[jb][pp + 2]));
                }
        }

        if (i + 1 < NTG) {
            stsA(i + 1);
            if (i + 2 < NTG) {
                ldgA(i + 2);
                cpB(i + 2);
                asm volatile("cp.async.wait_group 1;" ::: "memory");
            } else {
                asm volatile("cp.async.wait_group 0;" ::: "memory");
            }
        }
        GBAR(bar);
    }

    // ---- norms: both groups contribute (k split across groups) ----
    #pragma unroll
    for (int j = 0; j < 4; j++)
        atomicAdd(&xsq_s[ar + 32 * j], xs[j]);
    __syncthreads();                    // both groups done; ring now reusable

    // ---- split-k merge + fused epilogue ----
    float* stash = (float*)smem;        // [128][STASH_STRIDE]
    if (g == 1) {
        #pragma unroll
        for (int im = 0; im < 2; im++)
            #pragma unroll
            for (int hf = 0; hf < 2; hf++) {
                const int row = wm * 32 + im * 16 + hf * 8 + fr;
                #pragma unroll
                for (int j = 0; j < 8; j++) {
                    const int col = wn * 64 + j * 8 + fc;
                    *reinterpret_cast<float2*>(&stash[row * STASH_STRIDE + col]) =
                        make_float2(acc[im][j][hf * 2], acc[im][j][hf * 2 + 1]);
                }
            }
    }
    __syncthreads();
    if (g == 0) {
        #pragma unroll
        for (int im = 0; im < 2; im++)
            #pragma unroll
            for (int hf = 0; hf < 2; hf++) {
                const int row = wm * 32 + im * 16 + hf * 8 + fr;
                const float xq = xsq_s[row];
                float* orow = out + ((size_t)bm * BM + row) * KK + bn * BN;
                #pragma unroll
                for (int j = 0; j < 8; j++) {
                    const int col = wn * 64 + j * 8 + fc;
                    const float2 o = *reinterpret_cast<const float2*>(
                        &stash[row * STASH_STRIDE + col]);
                    const float cr0 = acc[im][j][hf * 2] + o.x;
                    const float cr1 = acc[im][j][hf * 2 + 1] + o.y;
                    const float d0 = sqrtf(fmaxf(xq + csq_s[col] - 2.f * cr0, EPS_F));
                    const float d1 = sqrtf(fmaxf(xq + csq_s[col + 1] - 2.f * cr1, EPS_F));
                    *reinterpret_cast<float2*>(orow + col) = make_float2(d0, d1);
                }
            }
    }
}

extern "C" void kernel_launch(void* const* d_in, const int* in_sizes, int n_in,
                              void* d_out, int out_size)
{
    const float* X = (const float*)d_in[0];   // inputs  [8192, 3072] fp32
    const float* C = (const float*)d_in[1];   // centers [256, 3072]  fp32
    float* out = (float*)d_out;               // [8192, 256] fp32

    prep_c_fast<<<32, 256>>>(C);              // warp-per-row, MLP=24

    cudaFuncSetAttribute(rbf_dual_kernel,
                         cudaFuncAttributeMaxDynamicSharedMemorySize, SMEM_BYTES);
    dim3 grid(KK / BN, BB / BM);              // (2, 64) = 128 CTAs
    rbf_dual_kernel<<<grid, NTHREADS, SMEM_BYTES>>>(X, out);
}